// round 17
// baseline (speedup 1.0000x reference)
#include <cuda_runtime.h>
#include <cuda_fp16.h>
#include <mma.h>
#include <cstdint>

using namespace nvcuda;

#define NN 100000
#define NE 600000
#define D  128
#define CAP 64

// ---------------- device scratch ----------------
__device__ int    g_cnt[NN];                              // zero-init; self-cleaned below
__device__ uint2  g_bucket[(size_t)NN * CAP];             // (src, weight_bits)
__device__ __align__(16) __half g_wt[2 * D * D];          // fp16 [Wl ; Wr]
__device__ __align__(16) __half g_x16[(size_t)NN * D];    // fp16(x)

// ---------------- cp.async helpers ----------------
__device__ __forceinline__ void cp_async16(uint32_t dst, const void* src) {
    asm volatile("cp.async.cg.shared.global [%0], [%1], 16;"
                 :: "r"(dst), "l"(src) : "memory");
}
__device__ __forceinline__ void cp_async16z(uint32_t dst, const void* src, uint32_t bytes) {
    asm volatile("cp.async.cg.shared.global [%0], [%1], 16, %2;"
                 :: "r"(dst), "l"(src), "r"(bytes) : "memory");
}
#define CP_COMMIT() asm volatile("cp.async.commit_group;" ::: "memory")
#define CP_WAIT(n)  asm volatile("cp.async.wait_group %0;" :: "n"(n) : "memory")

// ------- scatter edges into buckets (+ weight cvt + x -> fp16 cvt) ----------
#define SCAT_GRID 3125
__global__ void __launch_bounds__(256) scatter_kernel(
    const int* __restrict__ esrc,
    const int* __restrict__ edst,
    const float* __restrict__ ew,
    const float* __restrict__ wl,
    const float* __restrict__ wr,
    const float* __restrict__ x)
{
    if (blockIdx.x < 64) {
        int i = blockIdx.x * 256 + threadIdx.x;   // 0..16383
        g_wt[i]         = __float2half_rn(wl[i]);
        g_wt[D * D + i] = __float2half_rn(wr[i]);
    }
    // x -> fp16 (grid-stride; NN*D/4 = 3.2M float4)
    {
        const float4* x4 = (const float4*)x;
        uint2* o2 = (uint2*)g_x16;
        for (size_t i = (size_t)blockIdx.x * 256 + threadIdx.x;
             i < (size_t)NN * D / 4;
             i += (size_t)SCAT_GRID * 256) {
            float4 v = __ldg(&x4[i]);
            __half2 h0 = __floats2half2_rn(v.x, v.y);
            __half2 h1 = __floats2half2_rn(v.z, v.w);
            uint2 u;
            u.x = *(uint32_t*)&h0;
            u.y = *(uint32_t*)&h1;
            o2[i] = u;
        }
    }
    int e = blockIdx.x * 256 + threadIdx.x;
    if (e >= NE) return;
    int s = __ldg(&esrc[e]);
    int d = __ldg(&edst[e]);
    float w = __ldg(&ew[e]);
    int pos = atomicAdd(&g_cnt[d], 1);
    g_bucket[(size_t)d * CAP + pos] = make_uint2((unsigned)s, __float_as_uint(w));
}

// ---------------- fused gather + dual fp16 GEMM (B smem-resident) -------------
// out[tile] = agg(tile) @ Wl + x(tile) @ Wr + (bl+br)
#define BM 128
#define LDA 136     // halves
#define LDB 136     // halves
#define LDBI 136    // floats

// smem byte offsets
#define OFF_AS   0
#define OFF_B    (BM * LDA * 2)                      // 34816
#define OFF_BIAS (OFF_B + 256 * LDB * 2)             // +69632 = 104448
#define SM_BYTES (OFF_BIAS + 16 * LDBI * 4)          // +8704  = 113152

__global__ void __launch_bounds__(256, 2) fused_kernel(
    const float* __restrict__ bl,
    const float* __restrict__ br,
    float* __restrict__ out)
{
    extern __shared__ char smraw[];
    __half (*As)[LDA] = (__half(*)[LDA])(smraw + OFF_AS);
    __half* Bsm  = (__half*)(smraw + OFF_B);     // [256][LDB]
    float*  Bias = (float*) (smraw + OFF_BIAS);  // [16][LDBI]

    const int tid = threadIdx.x;
    const int wid = tid >> 5;
    const int lane = tid & 31;
    const int warp_m = wid & 3;    // 32-row group
    const int warp_n = wid >> 2;   // 64-col group
    const int m0 = blockIdx.x * BM;

    // ---- issue the ENTIRE B load (64KB); gather hides it ----
    {
        uint32_t b_base = (uint32_t)__cvta_generic_to_shared(Bsm);
        const int c8 = (tid & 15) * 8;
        const int r0 = tid >> 4;
        #pragma unroll
        for (int it = 0; it < 16; it++) {
            int row = r0 + it * 16;
            cp_async16(b_base + (row * LDB + c8) * 2,
                       &g_wt[(size_t)row * D + c8]);
        }
        CP_COMMIT();
    }

    // ---- bias replica tile (fp32) ----
    for (int s = tid; s < 16 * LDBI; s += 256) {
        int c = s % LDBI;
        Bias[s] = (c < 128) ? (bl[c] + br[c]) : 0.f;
    }

    // ---- phase 1: gather agg rows into As (fp16 x reads, fp32 acc -> fp16) ----
    {
        int node_row = wid * 16;
        for (int i = 0; i < 16; i++) {
            int row = node_row + i;
            int n = m0 + row;
            float4 a = make_float4(0.f, 0.f, 0.f, 0.f);
            if (n < NN) {
                int deg = __ldg(&g_cnt[n]);
                if (lane == 0) g_cnt[n] = 0;   // self-clean: restore invariant for next replay
                const uint2* bk = &g_bucket[(size_t)n * CAP];
                for (int j = 0; j < deg; j++) {
                    uint2 ent = __ldg(&bk[j]);
                    float w = __uint_as_float(ent.y);
                    uint2 u = __ldg((const uint2*)&g_x16[(size_t)ent.x * D + lane * 4]);
                    float2 f0 = __half22float2(*reinterpret_cast<__half2*>(&u.x));
                    float2 f1 = __half22float2(*reinterpret_cast<__half2*>(&u.y));
                    a.x += w * f0.x; a.y += w * f0.y;
                    a.z += w * f1.x; a.w += w * f1.y;
                }
            }
            __half2* dst = (__half2*)&As[row][lane * 4];
            dst[0] = __floats2half2_rn(a.x, a.y);
            dst[1] = __floats2half2_rn(a.z, a.w);
        }
    }
    CP_WAIT(0);          // B resident
    __syncthreads();     // As + B + Bias visible

    // ---- init accumulators from bias ----
    wmma::fragment<wmma::accumulator, 16, 16, 16, float> acc[2][4];
    #pragma unroll
    for (int i = 0; i < 2; i++)
        #pragma unroll
        for (int j = 0; j < 4; j++)
            wmma::load_matrix_sync(acc[i][j], &Bias[warp_n * 64 + j * 16], LDBI,
                                   wmma::mem_row_major);

    // ---- GEMM over one K-half: no barriers, no waits ----
    auto gemm_half = [&](int kbase) {
        #pragma unroll
        for (int kc = 0; kc < 8; kc++) {
            wmma::fragment<wmma::matrix_a, 16, 16, 16, __half, wmma::row_major> af[2];
            #pragma unroll
            for (int i = 0; i < 2; i++)
                wmma::load_matrix_sync(af[i], &As[warp_m * 32 + i * 16][kc * 16], LDA);
            #pragma unroll
            for (int j = 0; j < 4; j++) {
                wmma::fragment<wmma::matrix_b, 16, 16, 16, __half, wmma::row_major> bf;
                wmma::load_matrix_sync(bf,
                    &Bsm[(size_t)(kbase + kc * 16) * LDB + warp_n * 64 + j * 16], LDB);
                #pragma unroll
                for (int i = 0; i < 2; i++)
                    wmma::mma_sync(acc[i][j], af[i], bf, acc[i][j]);
            }
        }
    };

    // ---- phase 2: agg @ Wl ----
    gemm_half(0);

    // ---- phase 3: cp.async this CTA's fp16 x rows into As ----
    __syncthreads();
    {
        uint32_t as_base = (uint32_t)__cvta_generic_to_shared(&As[0][0]);
        #pragma unroll
        for (int it = 0; it < 8; it++) {
            int slot = tid + it * 256;        // 0..2047
            int row = slot >> 4;              // 0..127
            int c8  = (slot & 15) * 8;        // halves 0..120
            int gr = m0 + row;
            const __half* src = &g_x16[(size_t)(gr < NN ? gr : 0) * D + c8];
            cp_async16z(as_base + (row * LDA + c8) * 2, src, (gr < NN) ? 16u : 0u);
        }
        CP_COMMIT();
        CP_WAIT(0);
    }
    __syncthreads();

    // ---- phase 4: x @ Wr ----
    gemm_half(128);

    // ---- epilogue (NN % 16 == 0 -> tiles fully in or out) ----
    #pragma unroll
    for (int i = 0; i < 2; i++) {
        int row0 = m0 + warp_m * 32 + i * 16;
        if (row0 >= NN) continue;
        #pragma unroll
        for (int j = 0; j < 4; j++) {
            int col0 = warp_n * 64 + j * 16;
            wmma::store_matrix_sync(&out[(size_t)row0 * D + col0], acc[i][j], D,
                                    wmma::mem_row_major);
        }
    }
}

// ---------------- launch ----------------
extern "C" void kernel_launch(void* const* d_in, const int* in_sizes, int n_in,
                              void* d_out, int out_size)
{
    const float* x    = (const float*)d_in[0];
    const int*   esrc = (const int*)  d_in[1];
    const int*   edst = (const int*)  d_in[2];
    const float* ew   = (const float*)d_in[3];
    const float* wl   = (const float*)d_in[4];
    const float* bl   = (const float*)d_in[5];
    const float* wr   = (const float*)d_in[6];
    const float* br   = (const float*)d_in[7];
    float* out = (float*)d_out;

    static bool attr_set = false;
    if (!attr_set) {
        cudaFuncSetAttribute(fused_kernel,
                             cudaFuncAttributeMaxDynamicSharedMemorySize, SM_BYTES);
        attr_set = true;
    }

    scatter_kernel<<<SCAT_GRID, 256>>>(esrc, edst, ew, wl, wr, x);
    fused_kernel<<<(NN + BM - 1) / BM, 256, SM_BYTES>>>(bl, br, out);
}